// round 1
// baseline (speedup 1.0000x reference)
#include <cuda_runtime.h>
#include <cuda_bf16.h>
#include <math.h>

// Problem constants
constexpr int BB = 2;
constexpr int QQ = 2048;
constexpr int MM = 2048;
constexpr int HH = 16;
constexpr int DD = 64;
constexpr int HID = 1024;      // H*D
constexpr int KK = MM + QQ;    // 4096

// ---------------- scratch (device globals; no allocations allowed) ----------
__device__ float g_kvln[(size_t)BB * KK * HID];   // 32 MB
__device__ float g_qln [(size_t)BB * QQ * HID];   // 16 MB
__device__ float g_pe  [(size_t)KK * HID];        // 16 MB
__device__ float g_Qp  [(size_t)BB * QQ * HID];   // 16 MB
__device__ float g_Kp  [(size_t)BB * KK * HID];   // 32 MB
__device__ float g_Vp  [(size_t)BB * KK * HID];   // 32 MB
__device__ float g_Rel [(size_t)KK * HID];        // 16 MB
__device__ float g_attn[(size_t)BB * QQ * HID];   // 16 MB

// ---------------- LayerNorm over rows of length 1024 ------------------------
__device__ __forceinline__ void ln_row_1024(const float* __restrict__ src,
                                            float* __restrict__ dst,
                                            const float* __restrict__ gamma,
                                            const float* __restrict__ beta)
{
    __shared__ float red[16];
    int tid = threadIdx.x;                    // 256 threads, 4 floats each
    float4 v = ((const float4*)src)[tid];
    float s1 = v.x + v.y + v.z + v.w;
    float s2 = v.x*v.x + v.y*v.y + v.z*v.z + v.w*v.w;
#pragma unroll
    for (int off = 16; off; off >>= 1) {
        s1 += __shfl_xor_sync(0xffffffffu, s1, off);
        s2 += __shfl_xor_sync(0xffffffffu, s2, off);
    }
    if ((tid & 31) == 0) { red[tid >> 5] = s1; red[8 + (tid >> 5)] = s2; }
    __syncthreads();
    if (tid == 0) {
        float a = 0.f, b = 0.f;
#pragma unroll
        for (int i = 0; i < 8; i++) { a += red[i]; b += red[8 + i]; }
        float mu  = a * (1.0f / 1024.0f);
        float var = b * (1.0f / 1024.0f) - mu * mu;
        red[0] = mu;
        red[1] = rsqrtf(var + 1e-3f);
    }
    __syncthreads();
    float mu = red[0], sc = red[1];
    float4 g  = ((const float4*)gamma)[tid];
    float4 bb = ((const float4*)beta)[tid];
    float4 o;
    o.x = (v.x - mu) * sc * g.x + bb.x;
    o.y = (v.y - mu) * sc * g.y + bb.y;
    o.z = (v.z - mu) * sc * g.z + bb.z;
    o.w = (v.w - mu) * sc * g.w + bb.w;
    ((float4*)dst)[tid] = o;
}

__global__ __launch_bounds__(256)
void ln_kv_kernel(const float* __restrict__ mem, const float* __restrict__ qry,
                  const float* __restrict__ gamma, const float* __restrict__ beta,
                  float* __restrict__ out)
{
    int row = blockIdx.x;                 // 0 .. B*KK-1
    int b = row / KK, r = row % KK;
    const float* src = (r < MM) ? (mem + ((size_t)b * MM + r) * HID)
                                : (qry + ((size_t)b * QQ + (r - MM)) * HID);
    ln_row_1024(src, out + (size_t)row * HID, gamma, beta);
}

__global__ __launch_bounds__(256)
void ln_q_kernel(const float* __restrict__ qry,
                 const float* __restrict__ gamma, const float* __restrict__ beta,
                 float* __restrict__ out)
{
    int row = blockIdx.x;                 // 0 .. B*QQ-1
    ln_row_1024(qry + (size_t)row * HID, out + (size_t)row * HID, gamma, beta);
}

// ---------------- sinusoidal relative position embedding --------------------
__global__ __launch_bounds__(256)
void posemb_kernel(float* __restrict__ pe)
{
    int j = blockIdx.x;                   // 0 .. KK-1
    float pos = (float)(KK - 1 - j);
    const float c = -9.210340371976184f / 512.0f;   // -ln(10000)/512
    for (int i = threadIdx.x; i < 512; i += blockDim.x) {
        float invf = expf(c * (float)i);
        float ang  = pos * invf;
        pe[(size_t)j * HID + i]        = sinf(ang);
        pe[(size_t)j * HID + 512 + i]  = cosf(ang);
    }
}

// ---------------- SGEMM: C[M,1024] = A[M,1024] * B[1024,1024] ---------------
// 128x128 tile, K-step 8, 256 threads, 8x8 register micro-tile.
__global__ __launch_bounds__(256)
void sgemm_k1024(const float* __restrict__ A, const float* __restrict__ B,
                 float* __restrict__ C)
{
    const int N = 1024, K = 1024;
    __shared__ float As[8][128];
    __shared__ float Bs[8][128];
    int tid  = threadIdx.x;
    int row0 = blockIdx.y * 128;
    int col0 = blockIdx.x * 128;
    int aRow = tid >> 1;
    int aK4  = (tid & 1) << 2;
    int bRow = tid >> 5;
    int bCol = (tid & 31) << 2;
    int ty = tid >> 4, tx = tid & 15;

    float acc[8][8] = {};
    for (int k0 = 0; k0 < K; k0 += 8) {
        float4 av = *(const float4*)&A[(size_t)(row0 + aRow) * K + k0 + aK4];
        As[aK4 + 0][aRow] = av.x;
        As[aK4 + 1][aRow] = av.y;
        As[aK4 + 2][aRow] = av.z;
        As[aK4 + 3][aRow] = av.w;
        *(float4*)&Bs[bRow][bCol] =
            *(const float4*)&B[(size_t)(k0 + bRow) * N + col0 + bCol];
        __syncthreads();
#pragma unroll
        for (int kk = 0; kk < 8; kk++) {
            float ar[8], br[8];
#pragma unroll
            for (int i = 0; i < 8; i++) ar[i] = As[kk][ty * 8 + i];
#pragma unroll
            for (int j = 0; j < 8; j++) br[j] = Bs[kk][tx * 8 + j];
#pragma unroll
            for (int i = 0; i < 8; i++)
#pragma unroll
                for (int j = 0; j < 8; j++) acc[i][j] += ar[i] * br[j];
        }
        __syncthreads();
    }
#pragma unroll
    for (int i = 0; i < 8; i++) {
        size_t r = (size_t)(row0 + ty * 8 + i);
#pragma unroll
        for (int j = 0; j < 8; j += 4) {
            float4 v = make_float4(acc[i][j], acc[i][j+1], acc[i][j+2], acc[i][j+3]);
            *(float4*)&C[r * N + col0 + tx * 8 + j] = v;
        }
    }
}

// ---------------- fused relative attention (flash-style, fp32) --------------
// grid: (Q/64, B*H); block: 256 threads (16x16), 4x4(+4x8) register micro-tiles.
// smem (floats):
//   sQw [64 d][68]  q + r_w_bias  (d-major)
//   sQr [64 d][68]  q + r_r_bias
//   sKd [64 d][68]  K tile (d-major)
//   sV  [64 k][68]  V tile
//   sRd [64 d][132] rel window (128 rows)  -- aliased by sP [64 q][132] later
//   sBD [64 q][132] BD full-window GEMM output
constexpr int SMEM_FLOATS = 4352 * 4 + 8448 * 2;   // 34240
constexpr int SMEM_BYTES  = SMEM_FLOATS * 4;

__global__ __launch_bounds__(256)
void attn_kernel(const float* __restrict__ Qp, const float* __restrict__ Kp,
                 const float* __restrict__ Vp, const float* __restrict__ Rel,
                 const float* __restrict__ rwb, const float* __restrict__ rrb,
                 const float* __restrict__ span, float* __restrict__ Out)
{
    extern __shared__ float sm[];
    float* sQw = sm;
    float* sQr = sm + 4352;
    float* sKd = sm + 8704;
    float* sV  = sm + 13056;
    float* sRd = sm + 17408;
    float* sBD = sm + 25856;
    float* sP  = sRd;                       // alias (disjoint lifetimes)

    const int tid = threadIdx.x;
    const int tx = tid & 15, ty = tid >> 4;
    const int q0 = blockIdx.x * 64;
    const int bh = blockIdx.y;
    const int b = bh >> 4, h = bh & 15;
    const float spanv = span[h];

    // stage Q tile with biases (transposed to d-major)
    for (int idx = tid; idx < 64 * 64; idx += 256) {
        int qq = idx >> 6, d = idx & 63;
        float qv = Qp[((size_t)(b * QQ + q0 + qq)) * HID + h * 64 + d];
        sQw[d * 68 + qq] = qv + rwb[h * 64 + d];
        sQr[d * 68 + qq] = qv + rrb[h * 64 + d];
    }

    float o[4][4] = {};
    float mrun[4], lf[4], lm[4];
#pragma unroll
    for (int i = 0; i < 4; i++) { mrun[i] = -1e30f; lf[i] = 0.f; lm[i] = 0.f; }

    const int ntiles = 33 + blockIdx.x;     // covers k <= M + q0 + 63
    for (int t = 0; t < ntiles; t++) {
        const int k0 = t * 64;
        __syncthreads();                    // protect smem reuse (incl. Q stage on t=0)

        // stage K, V tiles
        for (int idx = tid; idx < 4096; idx += 256) {
            int kk = idx >> 6, d = idx & 63;
            size_t g = ((size_t)(b * KK + k0 + kk)) * HID + h * 64 + d;
            sKd[d * 68 + kk] = Kp[g];
            sV [kk * 68 + d] = Vp[g];
        }
        // stage rel window: rows jbase .. jbase+127 (zero pad past KK)
        int jbase = k0 + (QQ - 1) - (q0 + 63);
        for (int idx = tid; idx < 8192; idx += 256) {
            int jj = idx >> 6, d = idx & 63;
            int j = jbase + jj;
            sRd[d * 132 + jj] = (j < KK) ? Rel[(size_t)j * HID + h * 64 + d] : 0.f;
        }
        __syncthreads();

        // BD window GEMM: [64 q] x [128 j]
        {
            float bd[4][8] = {};
#pragma unroll 8
            for (int d = 0; d < 64; d++) {
                float a[4], r8[8];
#pragma unroll
                for (int i = 0; i < 4; i++) a[i] = sQr[d * 68 + ty * 4 + i];
#pragma unroll
                for (int j = 0; j < 8; j++) r8[j] = sRd[d * 132 + tx * 8 + j];
#pragma unroll
                for (int i = 0; i < 4; i++)
#pragma unroll
                    for (int j = 0; j < 8; j++) bd[i][j] += a[i] * r8[j];
            }
#pragma unroll
            for (int i = 0; i < 4; i++)
#pragma unroll
                for (int j = 0; j < 8; j++)
                    sBD[(ty * 4 + i) * 132 + tx * 8 + j] = bd[i][j];
        }
        __syncthreads();

        // AD GEMM + combine (diagonal BD remap) + mask
        float s[4][4] = {};
#pragma unroll 8
        for (int d = 0; d < 64; d++) {
            float a[4], kq[4];
#pragma unroll
            for (int i = 0; i < 4; i++) a[i] = sQw[d * 68 + ty * 4 + i];
#pragma unroll
            for (int j = 0; j < 4; j++) kq[j] = sKd[d * 68 + tx * 4 + j];
#pragma unroll
            for (int i = 0; i < 4; i++)
#pragma unroll
                for (int j = 0; j < 4; j++) s[i][j] += a[i] * kq[j];
        }
        float rmax[4];
#pragma unroll
        for (int i = 0; i < 4; i++) {
            int qq = ty * 4 + i, q = q0 + qq;
            rmax[i] = -1e30f;
#pragma unroll
            for (int j = 0; j < 4; j++) {
                int kk = tx * 4 + j, k = k0 + kk;
                float val = (s[i][j] + sBD[qq * 132 + kk + 63 - qq]) * (1.0f / 64.0f);
                val = (k <= MM + q) ? val : -1e30f;
                s[i][j] = val;
                rmax[i] = fmaxf(rmax[i], val);
            }
        }
#pragma unroll
        for (int i = 0; i < 4; i++)
#pragma unroll
            for (int off = 8; off; off >>= 1)
                rmax[i] = fmaxf(rmax[i], __shfl_xor_sync(0xffffffffu, rmax[i], off));

        float corr[4], lfa[4], lma[4];
#pragma unroll
        for (int i = 0; i < 4; i++) {
            float mnew = fmaxf(mrun[i], rmax[i]);
            corr[i] = __expf(mrun[i] - mnew);
            mrun[i] = mnew;
            lfa[i] = 0.f; lma[i] = 0.f;
        }
#pragma unroll
        for (int i = 0; i < 4; i++) {
            int qq = ty * 4 + i;
#pragma unroll
            for (int j = 0; j < 4; j++) {
                int k = k0 + tx * 4 + j;
                float e = __expf(s[i][j] - mrun[i]);     // masked -> exp(-inf)=0
                float mk = 1.0f;
                if (k >= MM)
                    mk = fminf(fmaxf(((float)(k - MM) + spanv * (float)QQ) * (1.0f / 33.0f),
                                     0.0f), 1.0f);
                float em = e * mk;
                lfa[i] += e;
                lma[i] += em;
                sP[qq * 132 + tx * 4 + j] = em;
            }
        }
#pragma unroll
        for (int i = 0; i < 4; i++) {
#pragma unroll
            for (int off = 8; off; off >>= 1) {
                lfa[i] += __shfl_xor_sync(0xffffffffu, lfa[i], off);
                lma[i] += __shfl_xor_sync(0xffffffffu, lma[i], off);
            }
            lf[i] = lf[i] * corr[i] + lfa[i];
            lm[i] = lm[i] * corr[i] + lma[i];
#pragma unroll
            for (int j = 0; j < 4; j++) o[i][j] *= corr[i];
        }
        __syncthreads();

        // PV GEMM
#pragma unroll 8
        for (int kk = 0; kk < 64; kk++) {
            float p[4], v[4];
#pragma unroll
            for (int i = 0; i < 4; i++) p[i] = sP[(ty * 4 + i) * 132 + kk];
#pragma unroll
            for (int j = 0; j < 4; j++) v[j] = sV[kk * 68 + tx * 4 + j];
#pragma unroll
            for (int i = 0; i < 4; i++)
#pragma unroll
                for (int j = 0; j < 4; j++) o[i][j] += p[i] * v[j];
        }
    }

    // finalize: divide by (masked_sum + 1e-8 * full_sum)  [exact vs reference]
#pragma unroll
    for (int i = 0; i < 4; i++) {
        float inv = 1.0f / (lm[i] + 1e-8f * lf[i]);
        int q = q0 + ty * 4 + i;
#pragma unroll
        for (int j = 0; j < 4; j++)
            Out[((size_t)(b * QQ + q)) * HID + h * 64 + tx * 4 + j] = o[i][j] * inv;
    }
}

// ---------------- launch -----------------------------------------------------
extern "C" void kernel_launch(void* const* d_in, const int* in_sizes, int n_in,
                              void* d_out, int out_size)
{
    const float* query     = (const float*)d_in[0];
    const float* memory    = (const float*)d_in[1];
    const float* Wq        = (const float*)d_in[2];
    const float* Wk        = (const float*)d_in[3];
    const float* Wv        = (const float*)d_in[4];
    const float* Wo        = (const float*)d_in[5];
    const float* Wr        = (const float*)d_in[6];
    const float* gamma_mem = (const float*)d_in[7];
    const float* beta_mem  = (const float*)d_in[8];
    const float* gamma_q   = (const float*)d_in[9];
    const float* beta_q    = (const float*)d_in[10];
    const float* rwb       = (const float*)d_in[11];
    const float* rrb       = (const float*)d_in[12];
    const float* span      = (const float*)d_in[13];
    float* out = (float*)d_out;

    float *kvln, *qln, *pe, *Qp, *Kp, *Vp, *Rel, *attn;
    cudaGetSymbolAddress((void**)&kvln, g_kvln);
    cudaGetSymbolAddress((void**)&qln,  g_qln);
    cudaGetSymbolAddress((void**)&pe,   g_pe);
    cudaGetSymbolAddress((void**)&Qp,   g_Qp);
    cudaGetSymbolAddress((void**)&Kp,   g_Kp);
    cudaGetSymbolAddress((void**)&Vp,   g_Vp);
    cudaGetSymbolAddress((void**)&Rel,  g_Rel);
    cudaGetSymbolAddress((void**)&attn, g_attn);

    cudaFuncSetAttribute(attn_kernel, cudaFuncAttributeMaxDynamicSharedMemorySize,
                         SMEM_BYTES);

    ln_kv_kernel<<<BB * KK, 256>>>(memory, query, gamma_mem, beta_mem, kvln);
    ln_q_kernel <<<BB * QQ, 256>>>(query, gamma_q, beta_q, qln);
    posemb_kernel<<<KK, 256>>>(pe);

    sgemm_k1024<<<dim3(8, (BB * QQ) / 128), 256>>>(qln,  Wq, Qp);
    sgemm_k1024<<<dim3(8, (BB * KK) / 128), 256>>>(kvln, Wk, Kp);
    sgemm_k1024<<<dim3(8, (BB * KK) / 128), 256>>>(kvln, Wv, Vp);
    sgemm_k1024<<<dim3(8, KK / 128),        256>>>(pe,   Wr, Rel);

    attn_kernel<<<dim3(QQ / 64, BB * HH), 256, SMEM_BYTES>>>(
        Qp, Kp, Vp, Rel, rwb, rrb, span, attn);

    sgemm_k1024<<<dim3(8, (BB * QQ) / 128), 256>>>(attn, Wo, out);
}

// round 2
// speedup vs baseline: 1.0987x; 1.0987x over previous
#include <cuda_runtime.h>
#include <cuda_bf16.h>
#include <math.h>

// Problem constants
constexpr int BB = 2;
constexpr int QQ = 2048;
constexpr int MM = 2048;
constexpr int HH = 16;
constexpr int DD = 64;
constexpr int HID = 1024;      // H*D
constexpr int KK = MM + QQ;    // 4096

// ---------------- packed f32x2 helpers (sm_103a FFMA2 path) ------------------
__device__ __forceinline__ unsigned long long pk2(float lo, float hi)
{
    unsigned long long r;
    asm("mov.b64 %0, {%1, %2};" : "=l"(r) : "f"(lo), "f"(hi));
    return r;
}
__device__ __forceinline__ void fma2(unsigned long long& d,
                                     unsigned long long a, unsigned long long b)
{
    asm("fma.rn.f32x2 %0, %1, %2, %3;" : "=l"(d) : "l"(a), "l"(b), "l"(d));
}
__device__ __forceinline__ float2 upk(unsigned long long v)
{
    float2 r;
    asm("mov.b64 {%0, %1}, %2;" : "=f"(r.x), "=f"(r.y) : "l"(v));
    return r;
}

// ---------------- scratch (device globals; no allocations allowed) ----------
__device__ float g_kvln[(size_t)BB * KK * HID];
__device__ float g_qln [(size_t)BB * QQ * HID];
__device__ float g_pe  [(size_t)KK * HID];
__device__ float g_Qp  [(size_t)BB * QQ * HID];
__device__ float g_Kp  [(size_t)BB * KK * HID];
__device__ float g_Vp  [(size_t)BB * KK * HID];
__device__ float g_Rel [(size_t)KK * HID];
__device__ float g_attn[(size_t)BB * QQ * HID];

// ---------------- LayerNorm over rows of length 1024 ------------------------
__device__ __forceinline__ void ln_row_1024(const float* __restrict__ src,
                                            float* __restrict__ dst,
                                            const float* __restrict__ gamma,
                                            const float* __restrict__ beta)
{
    __shared__ float red[16];
    int tid = threadIdx.x;                    // 256 threads, 4 floats each
    float4 v = ((const float4*)src)[tid];
    float s1 = v.x + v.y + v.z + v.w;
    float s2 = v.x*v.x + v.y*v.y + v.z*v.z + v.w*v.w;
#pragma unroll
    for (int off = 16; off; off >>= 1) {
        s1 += __shfl_xor_sync(0xffffffffu, s1, off);
        s2 += __shfl_xor_sync(0xffffffffu, s2, off);
    }
    if ((tid & 31) == 0) { red[tid >> 5] = s1; red[8 + (tid >> 5)] = s2; }
    __syncthreads();
    if (tid == 0) {
        float a = 0.f, b = 0.f;
#pragma unroll
        for (int i = 0; i < 8; i++) { a += red[i]; b += red[8 + i]; }
        float mu  = a * (1.0f / 1024.0f);
        float var = b * (1.0f / 1024.0f) - mu * mu;
        red[0] = mu;
        red[1] = rsqrtf(var + 1e-3f);
    }
    __syncthreads();
    float mu = red[0], sc = red[1];
    float4 g  = ((const float4*)gamma)[tid];
    float4 bb = ((const float4*)beta)[tid];
    float4 o;
    o.x = (v.x - mu) * sc * g.x + bb.x;
    o.y = (v.y - mu) * sc * g.y + bb.y;
    o.z = (v.z - mu) * sc * g.z + bb.z;
    o.w = (v.w - mu) * sc * g.w + bb.w;
    ((float4*)dst)[tid] = o;
}

__global__ __launch_bounds__(256)
void ln_kv_kernel(const float* __restrict__ mem, const float* __restrict__ qry,
                  const float* __restrict__ gamma, const float* __restrict__ beta,
                  float* __restrict__ out)
{
    int row = blockIdx.x;                 // 0 .. B*KK-1
    int b = row / KK, r = row % KK;
    const float* src = (r < MM) ? (mem + ((size_t)b * MM + r) * HID)
                                : (qry + ((size_t)b * QQ + (r - MM)) * HID);
    ln_row_1024(src, out + (size_t)row * HID, gamma, beta);
}

__global__ __launch_bounds__(256)
void ln_q_kernel(const float* __restrict__ qry,
                 const float* __restrict__ gamma, const float* __restrict__ beta,
                 float* __restrict__ out)
{
    int row = blockIdx.x;                 // 0 .. B*QQ-1
    ln_row_1024(qry + (size_t)row * HID, out + (size_t)row * HID, gamma, beta);
}

// ---------------- sinusoidal relative position embedding --------------------
__global__ __launch_bounds__(256)
void posemb_kernel(float* __restrict__ pe)
{
    int j = blockIdx.x;                   // 0 .. KK-1
    float pos = (float)(KK - 1 - j);
    const float c = -9.210340371976184f / 512.0f;   // -ln(10000)/512
    for (int i = threadIdx.x; i < 512; i += blockDim.x) {
        float invf = expf(c * (float)i);
        float ang  = pos * invf;
        pe[(size_t)j * HID + i]        = sinf(ang);
        pe[(size_t)j * HID + 512 + i]  = cosf(ang);
    }
}

// ---------------- SGEMM: C[M,1024] = A[M,1024] * B[1024,1024] ---------------
// 128x128 tile, K-step 8, 256 threads, 8x8 register micro-tile, f32x2 FMAs.
__global__ __launch_bounds__(256, 2)
void sgemm_k1024(const float* __restrict__ A, const float* __restrict__ B,
                 float* __restrict__ C)
{
    const int N = 1024, K = 1024;
    __shared__ float As[8][128];
    __shared__ float Bs[8][128];
    int tid  = threadIdx.x;
    int row0 = blockIdx.y * 128;
    int col0 = blockIdx.x * 128;
    int aRow = tid >> 1;
    int aK4  = (tid & 1) << 2;
    int bRow = tid >> 5;
    int bCol = (tid & 31) << 2;
    int ty = tid >> 4, tx = tid & 15;

    unsigned long long acc[8][4];
#pragma unroll
    for (int i = 0; i < 8; i++)
#pragma unroll
        for (int j = 0; j < 4; j++) acc[i][j] = 0ull;

    for (int k0 = 0; k0 < K; k0 += 8) {
        float4 av = *(const float4*)&A[(size_t)(row0 + aRow) * K + k0 + aK4];
        As[aK4 + 0][aRow] = av.x;
        As[aK4 + 1][aRow] = av.y;
        As[aK4 + 2][aRow] = av.z;
        As[aK4 + 3][aRow] = av.w;
        *(float4*)&Bs[bRow][bCol] =
            *(const float4*)&B[(size_t)(k0 + bRow) * N + col0 + bCol];
        __syncthreads();
#pragma unroll
        for (int kk = 0; kk < 8; kk++) {
            float4 a0 = *(const float4*)&As[kk][ty * 8];
            float4 a1 = *(const float4*)&As[kk][ty * 8 + 4];
            unsigned long long b01 = *(const unsigned long long*)&Bs[kk][tx * 8];
            unsigned long long b23 = *(const unsigned long long*)&Bs[kk][tx * 8 + 2];
            unsigned long long b45 = *(const unsigned long long*)&Bs[kk][tx * 8 + 4];
            unsigned long long b67 = *(const unsigned long long*)&Bs[kk][tx * 8 + 6];
            float ar[8] = {a0.x, a0.y, a0.z, a0.w, a1.x, a1.y, a1.z, a1.w};
#pragma unroll
            for (int i = 0; i < 8; i++) {
                unsigned long long aa = pk2(ar[i], ar[i]);
                fma2(acc[i][0], aa, b01);
                fma2(acc[i][1], aa, b23);
                fma2(acc[i][2], aa, b45);
                fma2(acc[i][3], aa, b67);
            }
        }
        __syncthreads();
    }
#pragma unroll
    for (int i = 0; i < 8; i++) {
        size_t r = (size_t)(row0 + ty * 8 + i);
        float2 p0 = upk(acc[i][0]), p1 = upk(acc[i][1]);
        float2 p2 = upk(acc[i][2]), p3 = upk(acc[i][3]);
        *(float4*)&C[r * N + col0 + tx * 8]     = make_float4(p0.x, p0.y, p1.x, p1.y);
        *(float4*)&C[r * N + col0 + tx * 8 + 4] = make_float4(p2.x, p2.y, p3.x, p3.y);
    }
}

// ---------------- fused relative attention (no-max softmax, f32x2) ----------
// grid: (Q/64, B*H); block 256 (16x16).
// smem (floats):
//   sQw [64 d][68]   q + r_w_bias (d-major)
//   sKd [64 d][68]   K tile (d-major)
//   sV  [64 k][68]   V tile
//   sRd [64 d][132]  rel window (aliased by sBD [64 q][132])
//   sP  [64 q][68]   masked exp weights
//   sDl [64]         rrb - rwb per d
constexpr int SM_QW = 0;
constexpr int SM_KD = 4352;
constexpr int SM_V  = 8704;
constexpr int SM_RD = 13056;
constexpr int SM_P  = 21504;
constexpr int SM_DL = 25856;
constexpr int SMEM_FLOATS = 25920;
constexpr int SMEM_BYTES  = SMEM_FLOATS * 4;     // 103,680 B -> 2 CTAs/SM

__global__ __launch_bounds__(256, 2)
void attn_kernel(const float* __restrict__ Qp, const float* __restrict__ Kp,
                 const float* __restrict__ Vp, const float* __restrict__ Rel,
                 const float* __restrict__ rwb, const float* __restrict__ rrb,
                 const float* __restrict__ span, float* __restrict__ Out)
{
    extern __shared__ float sm[];
    float* sQw = sm + SM_QW;
    float* sKd = sm + SM_KD;
    float* sV  = sm + SM_V;
    float* sRd = sm + SM_RD;
    float* sBD = sRd;                    // alias (disjoint lifetimes, sync-fenced)
    float* sP  = sm + SM_P;
    float* sDl = sm + SM_DL;

    const int tid = threadIdx.x;
    const int tx = tid & 15, ty = tid >> 4;
    const int q0 = blockIdx.x * 64;
    const int bh = blockIdx.y;
    const int b = bh >> 4, h = bh & 15;
    const float spanv = span[h];

    if (tid < 64) sDl[tid] = rrb[h * 64 + tid] - rwb[h * 64 + tid];
    // stage Q tile with r_w_bias (transposed to d-major)
    for (int idx = tid; idx < 1024; idx += 256) {
        int qq = idx >> 4, d4 = (idx & 15) << 2;
        float4 qv = *(const float4*)&Qp[((size_t)(b * QQ + q0 + qq)) * HID + h * 64 + d4];
        float4 wb = *(const float4*)&rwb[h * 64 + d4];
        sQw[(d4 + 0) * 68 + qq] = qv.x + wb.x;
        sQw[(d4 + 1) * 68 + qq] = qv.y + wb.y;
        sQw[(d4 + 2) * 68 + qq] = qv.z + wb.z;
        sQw[(d4 + 3) * 68 + qq] = qv.w + wb.w;
    }

    unsigned long long o[4][2];
    float lf[4], lm[4];
#pragma unroll
    for (int i = 0; i < 4; i++) { o[i][0] = 0ull; o[i][1] = 0ull; lf[i] = 0.f; lm[i] = 0.f; }

    const int ntiles = 33 + blockIdx.x;     // covers k <= M + q0 + 63
    for (int t = 0; t < ntiles; t++) {
        const int k0 = t * 64;
        __syncthreads();                    // staging vs prior-tile reads (and Q stage)

        // stage K (d-major), V (k-major)
        for (int idx = tid; idx < 1024; idx += 256) {
            int kk = idx >> 4, d4 = (idx & 15) << 2;
            size_t g = ((size_t)(b * KK + k0 + kk)) * HID + h * 64 + d4;
            float4 kv4 = *(const float4*)&Kp[g];
            sKd[(d4 + 0) * 68 + kk] = kv4.x;
            sKd[(d4 + 1) * 68 + kk] = kv4.y;
            sKd[(d4 + 2) * 68 + kk] = kv4.z;
            sKd[(d4 + 3) * 68 + kk] = kv4.w;
            *(float4*)&sV[kk * 68 + d4] = *(const float4*)&Vp[g];
        }
        // stage rel window rows jbase..jbase+127 (d-major, zero pad past KK)
        int jbase = k0 + (QQ - 1) - (q0 + 63);
        for (int idx = tid; idx < 2048; idx += 256) {
            int jj = idx >> 4, d4 = (idx & 15) << 2;
            int j = jbase + jj;
            if (j < KK) {
                float4 rv = *(const float4*)&Rel[(size_t)j * HID + h * 64 + d4];
                sRd[(d4 + 0) * 132 + jj] = rv.x;
                sRd[(d4 + 1) * 132 + jj] = rv.y;
                sRd[(d4 + 2) * 132 + jj] = rv.z;
                sRd[(d4 + 3) * 132 + jj] = rv.w;
            } else {
                sRd[(d4 + 0) * 132 + jj] = 0.f;
                sRd[(d4 + 1) * 132 + jj] = 0.f;
                sRd[(d4 + 2) * 132 + jj] = 0.f;
                sRd[(d4 + 3) * 132 + jj] = 0.f;
            }
        }
        __syncthreads();

        // BD window GEMM: [64 q] x [128 j], accumulators in registers
        unsigned long long bd[4][4];
#pragma unroll
        for (int i = 0; i < 4; i++)
#pragma unroll
            for (int m = 0; m < 4; m++) bd[i][m] = 0ull;
#pragma unroll 8
        for (int d = 0; d < 64; d++) {
            float4 a4 = *(const float4*)&sQw[d * 68 + 4 * ty];
            float dl = sDl[d];
            unsigned long long r0 = *(const unsigned long long*)&sRd[d * 132 + 8 * tx];
            unsigned long long r1 = *(const unsigned long long*)&sRd[d * 132 + 8 * tx + 2];
            unsigned long long r2 = *(const unsigned long long*)&sRd[d * 132 + 8 * tx + 4];
            unsigned long long r3 = *(const unsigned long long*)&sRd[d * 132 + 8 * tx + 6];
            float av[4] = {a4.x + dl, a4.y + dl, a4.z + dl, a4.w + dl};
#pragma unroll
            for (int i = 0; i < 4; i++) {
                unsigned long long aa = pk2(av[i], av[i]);
                fma2(bd[i][0], aa, r0);
                fma2(bd[i][1], aa, r1);
                fma2(bd[i][2], aa, r2);
                fma2(bd[i][3], aa, r3);
            }
        }
        __syncthreads();                    // all sRd reads done before overwrite
        // spill bd into sBD (aliased over sRd)
#pragma unroll
        for (int i = 0; i < 4; i++) {
            int qq = 4 * ty + i;
#pragma unroll
            for (int m = 0; m < 4; m++)
                *(unsigned long long*)&sBD[qq * 132 + 8 * tx + 2 * m] = bd[i][m];
        }
        __syncthreads();

        // AD GEMM
        unsigned long long s[4][2];
#pragma unroll
        for (int i = 0; i < 4; i++) { s[i][0] = 0ull; s[i][1] = 0ull; }
#pragma unroll 8
        for (int d = 0; d < 64; d++) {
            float4 a4 = *(const float4*)&sQw[d * 68 + 4 * ty];
            unsigned long long k01 = *(const unsigned long long*)&sKd[d * 68 + 4 * tx];
            unsigned long long k23 = *(const unsigned long long*)&sKd[d * 68 + 4 * tx + 2];
            float av[4] = {a4.x, a4.y, a4.z, a4.w};
#pragma unroll
            for (int i = 0; i < 4; i++) {
                unsigned long long aa = pk2(av[i], av[i]);
                fma2(s[i][0], aa, k01);
                fma2(s[i][1], aa, k23);
            }
        }

        // combine: BD diagonal remap + mask + exp (no max-shift needed:
        // logits are bounded ~|1| for this problem, exp cannot overflow)
        float mk[4];
#pragma unroll
        for (int j = 0; j < 4; j++) {
            int k = k0 + 4 * tx + j;
            mk[j] = (k >= MM)
                ? fminf(fmaxf(((float)(k - MM) + spanv * (float)QQ) * (1.0f / 33.0f), 0.0f), 1.0f)
                : 1.0f;
        }
        const bool lastTile = (t == ntiles - 1);
#pragma unroll
        for (int i = 0; i < 4; i++) {
            int qq = 4 * ty + i, q = q0 + qq;
            float2 s01 = upk(s[i][0]), s23 = upk(s[i][1]);
            float sv[4] = {s01.x, s01.y, s23.x, s23.y};
#pragma unroll
            for (int j = 0; j < 4; j++) {
                int kk = 4 * tx + j;
                float val = (sv[j] + sBD[qq * 132 + kk + 63 - qq]) * (1.0f / 64.0f);
                float e = __expf(val);
                if (lastTile && (k0 + kk > MM + q)) e = 0.f;
                float em = e * mk[j];
                lf[i] += e;
                lm[i] += em;
                sP[qq * 68 + kk] = em;
            }
        }
        __syncthreads();

        // PV GEMM
#pragma unroll 8
        for (int kk = 0; kk < 64; kk++) {
            unsigned long long v01 = *(const unsigned long long*)&sV[kk * 68 + 4 * tx];
            unsigned long long v23 = *(const unsigned long long*)&sV[kk * 68 + 4 * tx + 2];
#pragma unroll
            for (int i = 0; i < 4; i++) {
                float p = sP[(4 * ty + i) * 68 + kk];
                unsigned long long pp = pk2(p, p);
                fma2(o[i][0], pp, v01);
                fma2(o[i][1], pp, v23);
            }
        }
    }

    // reduce lf/lm across tx (16 lanes within each half-warp row group)
#pragma unroll
    for (int i = 0; i < 4; i++) {
#pragma unroll
        for (int off = 8; off; off >>= 1) {
            lf[i] += __shfl_xor_sync(0xffffffffu, lf[i], off);
            lm[i] += __shfl_xor_sync(0xffffffffu, lm[i], off);
        }
    }

    // finalize: divide by (masked_sum + 1e-8 * full_sum)  [exact vs reference]
#pragma unroll
    for (int i = 0; i < 4; i++) {
        float inv = 1.0f / (lm[i] + 1e-8f * lf[i]);
        int q = q0 + 4 * ty + i;
        float2 o01 = upk(o[i][0]), o23 = upk(o[i][1]);
        *(float4*)&Out[((size_t)(b * QQ + q)) * HID + h * 64 + 4 * tx] =
            make_float4(o01.x * inv, o01.y * inv, o23.x * inv, o23.y * inv);
    }
}

// ---------------- launch -----------------------------------------------------
extern "C" void kernel_launch(void* const* d_in, const int* in_sizes, int n_in,
                              void* d_out, int out_size)
{
    const float* query     = (const float*)d_in[0];
    const float* memory    = (const float*)d_in[1];
    const float* Wq        = (const float*)d_in[2];
    const float* Wk        = (const float*)d_in[3];
    const float* Wv        = (const float*)d_in[4];
    const float* Wo        = (const float*)d_in[5];
    const float* Wr        = (const float*)d_in[6];
    const float* gamma_mem = (const float*)d_in[7];
    const float* beta_mem  = (const float*)d_in[8];
    const float* gamma_q   = (const float*)d_in[9];
    const float* beta_q    = (const float*)d_in[10];
    const float* rwb       = (const float*)d_in[11];
    const float* rrb       = (const float*)d_in[12];
    const float* span      = (const float*)d_in[13];
    float* out = (float*)d_out;

    float *kvln, *qln, *pe, *Qp, *Kp, *Vp, *Rel, *attn;
    cudaGetSymbolAddress((void**)&kvln, g_kvln);
    cudaGetSymbolAddress((void**)&qln,  g_qln);
    cudaGetSymbolAddress((void**)&pe,   g_pe);
    cudaGetSymbolAddress((void**)&Qp,   g_Qp);
    cudaGetSymbolAddress((void**)&Kp,   g_Kp);
    cudaGetSymbolAddress((void**)&Vp,   g_Vp);
    cudaGetSymbolAddress((void**)&Rel,  g_Rel);
    cudaGetSymbolAddress((void**)&attn, g_attn);

    cudaFuncSetAttribute(attn_kernel, cudaFuncAttributeMaxDynamicSharedMemorySize,
                         SMEM_BYTES);

    ln_kv_kernel<<<BB * KK, 256>>>(memory, query, gamma_mem, beta_mem, kvln);
    ln_q_kernel <<<BB * QQ, 256>>>(query, gamma_q, beta_q, qln);
    posemb_kernel<<<KK, 256>>>(pe);

    sgemm_k1024<<<dim3(8, (BB * QQ) / 128), 256>>>(qln,  Wq, Qp);
    sgemm_k1024<<<dim3(8, (BB * KK) / 128), 256>>>(kvln, Wk, Kp);
    sgemm_k1024<<<dim3(8, (BB * KK) / 128), 256>>>(kvln, Wv, Vp);
    sgemm_k1024<<<dim3(8, KK / 128),        256>>>(pe,   Wr, Rel);

    attn_kernel<<<dim3(QQ / 64, BB * HH), 256, SMEM_BYTES>>>(
        Qp, Kp, Vp, Rel, rwb, rrb, span, attn);

    sgemm_k1024<<<dim3(8, (BB * QQ) / 128), 256>>>(attn, Wo, out);
}

// round 4
// speedup vs baseline: 2.6217x; 2.3862x over previous
#include <cuda_runtime.h>
#include <cuda_bf16.h>
#include <math.h>
#include <stdint.h>

// Problem constants
constexpr int BB = 2;
constexpr int QQ = 2048;
constexpr int MM = 2048;
constexpr int HH = 16;
constexpr int HID = 1024;      // H*D
constexpr int KK = MM + QQ;    // 4096

// ---------------- tf32 mma helpers ------------------------------------------
__device__ __forceinline__ uint32_t f2tf(float f)
{
    uint32_t r;
    asm("cvt.rna.tf32.f32 %0, %1;" : "=r"(r) : "f"(f));
    return r;
}
__device__ __forceinline__ void mma_tf32(float4& c, const uint32_t* a, const uint32_t* b)
{
    asm volatile("mma.sync.aligned.m16n8k8.row.col.f32.tf32.tf32.f32 "
                 "{%0,%1,%2,%3}, {%4,%5,%6,%7}, {%8,%9}, {%0,%1,%2,%3};\n"
                 : "+f"(c.x), "+f"(c.y), "+f"(c.z), "+f"(c.w)
                 : "r"(a[0]), "r"(a[1]), "r"(a[2]), "r"(a[3]),
                   "r"(b[0]), "r"(b[1]));
}

// ---------------- scratch (device globals; no allocations allowed) ----------
__device__ float g_kvln[(size_t)BB * KK * HID];
__device__ float g_qln [(size_t)BB * QQ * HID];
__device__ float g_pe  [(size_t)KK * HID];
__device__ float g_Qp  [(size_t)BB * QQ * HID];
__device__ float g_Kp  [(size_t)BB * KK * HID];
__device__ float g_Vp  [(size_t)BB * KK * HID];
__device__ float g_Rel [(size_t)KK * HID];
__device__ float g_attn[(size_t)BB * QQ * HID];

// ---------------- LayerNorm over rows of length 1024 ------------------------
__device__ __forceinline__ void ln_row_1024(const float* __restrict__ src,
                                            float* __restrict__ dst,
                                            const float* __restrict__ gamma,
                                            const float* __restrict__ beta)
{
    __shared__ float red[16];
    int tid = threadIdx.x;                    // 256 threads, 4 floats each
    float4 v = ((const float4*)src)[tid];
    float s1 = v.x + v.y + v.z + v.w;
    float s2 = v.x*v.x + v.y*v.y + v.z*v.z + v.w*v.w;
#pragma unroll
    for (int off = 16; off; off >>= 1) {
        s1 += __shfl_xor_sync(0xffffffffu, s1, off);
        s2 += __shfl_xor_sync(0xffffffffu, s2, off);
    }
    if ((tid & 31) == 0) { red[tid >> 5] = s1; red[8 + (tid >> 5)] = s2; }
    __syncthreads();
    if (tid == 0) {
        float a = 0.f, b = 0.f;
#pragma unroll
        for (int i = 0; i < 8; i++) { a += red[i]; b += red[8 + i]; }
        float mu  = a * (1.0f / 1024.0f);
        float var = b * (1.0f / 1024.0f) - mu * mu;
        red[0] = mu;
        red[1] = rsqrtf(var + 1e-3f);
    }
    __syncthreads();
    float mu = red[0], sc = red[1];
    float4 g  = ((const float4*)gamma)[tid];
    float4 bb = ((const float4*)beta)[tid];
    float4 o;
    o.x = (v.x - mu) * sc * g.x + bb.x;
    o.y = (v.y - mu) * sc * g.y + bb.y;
    o.z = (v.z - mu) * sc * g.z + bb.z;
    o.w = (v.w - mu) * sc * g.w + bb.w;
    ((float4*)dst)[tid] = o;
}

__global__ __launch_bounds__(256)
void ln_kv_kernel(const float* __restrict__ mem, const float* __restrict__ qry,
                  const float* __restrict__ gamma, const float* __restrict__ beta,
                  float* __restrict__ out)
{
    int row = blockIdx.x;
    int b = row / KK, r = row % KK;
    const float* src = (r < MM) ? (mem + ((size_t)b * MM + r) * HID)
                                : (qry + ((size_t)b * QQ + (r - MM)) * HID);
    ln_row_1024(src, out + (size_t)row * HID, gamma, beta);
}

__global__ __launch_bounds__(256)
void ln_q_kernel(const float* __restrict__ qry,
                 const float* __restrict__ gamma, const float* __restrict__ beta,
                 float* __restrict__ out)
{
    int row = blockIdx.x;
    ln_row_1024(qry + (size_t)row * HID, out + (size_t)row * HID, gamma, beta);
}

// ---------------- sinusoidal relative position embedding --------------------
__global__ __launch_bounds__(256)
void posemb_kernel(float* __restrict__ pe)
{
    int j = blockIdx.x;
    float pos = (float)(KK - 1 - j);
    const float c = -9.210340371976184f / 512.0f;   // -ln(10000)/512
    for (int i = threadIdx.x; i < 512; i += blockDim.x) {
        float invf = expf(c * (float)i);
        float ang  = pos * invf;
        pe[(size_t)j * HID + i]        = sinf(ang);
        pe[(size_t)j * HID + 512 + i]  = cosf(ang);
    }
}

// ---------------- tf32 SGEMM: C[M,1024] = A[M,1024]*B[1024,1024] ------------
// 128x128 tile, BK=16, 8 warps (2m x 4n), warp tile 64x32, m16n8k8 mma.
__global__ __launch_bounds__(256, 2)
void sgemm_tf32(const float* __restrict__ A, const float* __restrict__ B,
                float* __restrict__ C)
{
    __shared__ uint32_t As[128 * 20];   // [m][k] stride 20 (20g+tg distinct mod 32)
    __shared__ uint32_t Bs[16 * 136];   // [k][n] stride 136 (8tg+g distinct mod 32)
    const int tid = threadIdx.x;
    const int lane = tid & 31, wid = tid >> 5;
    const int g = lane >> 2, tg = lane & 3;
    const int wm = (wid & 1) * 64, wn = (wid >> 1) * 32;
    const int row0 = blockIdx.y * 128, col0 = blockIdx.x * 128;

    float4 acc[4][4];
#pragma unroll
    for (int i = 0; i < 4; i++)
#pragma unroll
        for (int j = 0; j < 4; j++) acc[i][j] = make_float4(0.f, 0.f, 0.f, 0.f);

    for (int k0 = 0; k0 < 1024; k0 += 16) {
#pragma unroll
        for (int l = 0; l < 2; l++) {
            int f4 = tid + l * 256;
            int ar = f4 >> 2, ac = (f4 & 3) << 2;
            float4 av = *(const float4*)&A[(size_t)(row0 + ar) * 1024 + k0 + ac];
            *(uint4*)&As[ar * 20 + ac] =
                make_uint4(f2tf(av.x), f2tf(av.y), f2tf(av.z), f2tf(av.w));
            int br = f4 >> 5, bc = (f4 & 31) << 2;
            float4 bv = *(const float4*)&B[(size_t)(k0 + br) * 1024 + col0 + bc];
            *(uint4*)&Bs[br * 136 + bc] =
                make_uint4(f2tf(bv.x), f2tf(bv.y), f2tf(bv.z), f2tf(bv.w));
        }
        __syncthreads();
#pragma unroll
        for (int kk = 0; kk < 16; kk += 8) {
            uint32_t af[4][4], bf[4][2];
#pragma unroll
            for (int mf = 0; mf < 4; mf++) {
                int m = wm + mf * 16;
                af[mf][0] = As[(m + g) * 20 + kk + tg];
                af[mf][1] = As[(m + g + 8) * 20 + kk + tg];
                af[mf][2] = As[(m + g) * 20 + kk + tg + 4];
                af[mf][3] = As[(m + g + 8) * 20 + kk + tg + 4];
            }
#pragma unroll
            for (int nf = 0; nf < 4; nf++) {
                int n = wn + nf * 8;
                bf[nf][0] = Bs[(kk + tg) * 136 + n + g];
                bf[nf][1] = Bs[(kk + tg + 4) * 136 + n + g];
            }
#pragma unroll
            for (int mf = 0; mf < 4; mf++)
#pragma unroll
                for (int nf = 0; nf < 4; nf++)
                    mma_tf32(acc[mf][nf], af[mf], bf[nf]);
        }
        __syncthreads();
    }
#pragma unroll
    for (int mf = 0; mf < 4; mf++) {
#pragma unroll
        for (int nf = 0; nf < 4; nf++) {
            int r = row0 + wm + mf * 16 + g;
            int c = col0 + wn + nf * 8 + 2 * tg;
            *(float2*)&C[(size_t)r * 1024 + c] = make_float2(acc[mf][nf].x, acc[mf][nf].y);
            *(float2*)&C[(size_t)(r + 8) * 1024 + c] = make_float2(acc[mf][nf].z, acc[mf][nf].w);
        }
    }
}

// ---------------- fused relative attention (tf32 mma, transposed tiles) -----
// grid: (Q/64, B*H); 256 threads, 8 warps.
// All tile GEMMs transposed: S^T = K*Qw^T, BD^T = Rel*Qw^T (+rank-1 bd1),
// O^T = V^T * P^T.  Staging is pure row-major (no per-tile transposes).
// smem (float units):
constexpr int AT_SQ  = 0;       // Qw^T [64 d][72]  tf32  (B-op, stride%32==8)
constexpr int AT_SK  = 4608;    // K    [64 k][68]  tf32  (A-op, stride%32==4)
constexpr int AT_SV  = 8960;    // V    [64 k][72]  tf32  (accessed B-style)
constexpr int AT_SR  = 13568;   // Rel  [128 j][68] tf32  / BD^T f32 (alias)
constexpr int AT_SPT = 22272;   // P^T  [64 k][72]  tf32
constexpr int AT_SB1 = 26880;   // bd1  [128] f32
constexpr int AT_SDL = 27008;   // dl   [64]  f32
constexpr int AT_SRM = 27072;   // lm red [4][64]
constexpr int AT_SRF = 27328;   // lf red [4][64]
constexpr int AT_SIV = 27584;   // inv  [64]
constexpr int AT_TOT = 27648;
constexpr int ATTN_SMEM_BYTES = AT_TOT * 4;     // 110,592 B -> 2 CTAs/SM

__global__ __launch_bounds__(256, 2)
void attn_tf32(const float* __restrict__ Qp, const float* __restrict__ Kp,
               const float* __restrict__ Vp, const float* __restrict__ Rel,
               const float* __restrict__ rwb, const float* __restrict__ rrb,
               const float* __restrict__ span, float* __restrict__ Out)
{
    extern __shared__ float sm[];
    uint32_t* uQ  = (uint32_t*)(sm + AT_SQ);
    uint32_t* uK  = (uint32_t*)(sm + AT_SK);
    uint32_t* uV  = (uint32_t*)(sm + AT_SV);
    uint32_t* uR  = (uint32_t*)(sm + AT_SR);
    float*   sBDT = sm + AT_SR;                  // alias over Rel
    uint32_t* uPT = (uint32_t*)(sm + AT_SPT);
    float* sB1 = sm + AT_SB1;
    float* sDl = sm + AT_SDL;
    float* sRM = sm + AT_SRM;
    float* sRF = sm + AT_SRF;
    float* sIv = sm + AT_SIV;

    const int tid = threadIdx.x;
    const int lane = tid & 31, wid = tid >> 5;
    const int g = lane >> 2, tg = lane & 3;
    const int wm = wid & 3;            // key/d strip (x16) for AD / PV
    const int wn = wid >> 2;           // q half (x32)
    const int q0 = blockIdx.x * 64;
    const int b = blockIdx.y >> 4, h = blockIdx.y & 15;
    const float spanv = span[h];

    if (tid < 64) sDl[tid] = rrb[h * 64 + tid] - rwb[h * 64 + tid];

    // stage Qw^T = (q + r_w_bias)^T, tf32 (once per CTA)
    for (int idx = tid; idx < 1024; idx += 256) {
        int qq = idx >> 4, d4 = (idx & 15) << 2;
        float4 qv = *(const float4*)&Qp[((size_t)(b * QQ + q0 + qq)) * HID + h * 64 + d4];
        float4 wb = *(const float4*)&rwb[h * 64 + d4];
        uQ[(d4 + 0) * 72 + qq] = f2tf(qv.x + wb.x);
        uQ[(d4 + 1) * 72 + qq] = f2tf(qv.y + wb.y);
        uQ[(d4 + 2) * 72 + qq] = f2tf(qv.z + wb.z);
        uQ[(d4 + 3) * 72 + qq] = f2tf(qv.w + wb.w);
    }

    float4 o[4];                       // out^T frags (d strip x q)
#pragma unroll
    for (int i = 0; i < 4; i++) o[i] = make_float4(0.f, 0.f, 0.f, 0.f);
    float lfp[8], lmp[8];
#pragma unroll
    for (int i = 0; i < 8; i++) { lfp[i] = 0.f; lmp[i] = 0.f; }

    const int ntiles = 33 + blockIdx.x;
    for (int t = 0; t < ntiles; t++) {
        const int k0 = t * 64;
        __syncthreads();               // prior-tile reads done (and Q stage at t=0)

        // stage K [key][68], V [key][72] (row-major, tf32)
        for (int idx = tid; idx < 1024; idx += 256) {
            int kk = idx >> 4, d4 = (idx & 15) << 2;
            size_t gofs = ((size_t)(b * KK + k0 + kk)) * HID + h * 64 + d4;
            float4 kv = *(const float4*)&Kp[gofs];
            *(uint4*)&uK[kk * 68 + d4] =
                make_uint4(f2tf(kv.x), f2tf(kv.y), f2tf(kv.z), f2tf(kv.w));
            float4 vv = *(const float4*)&Vp[gofs];
            *(uint4*)&uV[kk * 72 + d4] =
                make_uint4(f2tf(vv.x), f2tf(vv.y), f2tf(vv.z), f2tf(vv.w));
        }
        // stage Rel window [j][68], rows jbase..jbase+127, zero-pad past KK
        const int jbase = k0 + (QQ - 1) - (q0 + 63);
        for (int idx = tid; idx < 2048; idx += 256) {
            int jj = idx >> 4, d4 = (idx & 15) << 2;
            int j = jbase + jj;
            uint4 rt = make_uint4(0u, 0u, 0u, 0u);
            if (j < KK) {
                float4 rv = *(const float4*)&Rel[(size_t)j * HID + h * 64 + d4];
                rt = make_uint4(f2tf(rv.x), f2tf(rv.y), f2tf(rv.z), f2tf(rv.w));
            }
            *(uint4*)&uR[jj * 68 + d4] = rt;
        }
        __syncthreads();

        // bd1[j] = sum_d Rel[j][d] * dl[d]   (rank-1 r_r_bias correction)
        if (tid < 128) {
            const float* rr = (const float*)&uR[tid * 68];
            float s = 0.f;
#pragma unroll
            for (int d4 = 0; d4 < 64; d4 += 4) {
                float4 r4 = *(const float4*)&rr[d4];
                float4 dl4 = *(const float4*)&sDl[d4];
                s += r4.x * dl4.x + r4.y * dl4.y + r4.z * dl4.z + r4.w * dl4.w;
            }
            sB1[tid] = s;
        }

        // AD^T + BD^T mma (shared B-operand = Qw^T)
        float4 sf[4];                  // S^T frags (key strip x q)
        float4 bdf[8];                 // BD^T frags (j strip x 64 q)
#pragma unroll
        for (int i = 0; i < 4; i++) sf[i] = make_float4(0.f, 0.f, 0.f, 0.f);
#pragma unroll
        for (int i = 0; i < 8; i++) bdf[i] = make_float4(0.f, 0.f, 0.f, 0.f);
#pragma unroll
        for (int ks = 0; ks < 64; ks += 8) {
            uint32_t bq[8][2];
#pragma unroll
            for (int nf = 0; nf < 8; nf++) {
                int n = nf * 8 + g;
                bq[nf][0] = uQ[(ks + tg) * 72 + n];
                bq[nf][1] = uQ[(ks + tg + 4) * 72 + n];
            }
            uint32_t ak[4], ar[4];
            {
                int m = wm * 16;
                ak[0] = uK[(m + g) * 68 + ks + tg];
                ak[1] = uK[(m + g + 8) * 68 + ks + tg];
                ak[2] = uK[(m + g) * 68 + ks + tg + 4];
                ak[3] = uK[(m + g + 8) * 68 + ks + tg + 4];
            }
            {
                int m = wid * 16;
                ar[0] = uR[(m + g) * 68 + ks + tg];
                ar[1] = uR[(m + g + 8) * 68 + ks + tg];
                ar[2] = uR[(m + g) * 68 + ks + tg + 4];
                ar[3] = uR[(m + g + 8) * 68 + ks + tg + 4];
            }
#pragma unroll
            for (int nf = 0; nf < 4; nf++)
                mma_tf32(sf[nf], ak, bq[wn * 4 + nf]);
#pragma unroll
            for (int nf = 0; nf < 8; nf++)
                mma_tf32(bdf[nf], ar, bq[nf]);
        }
        __syncthreads();               // all uR reads done (mma + bd1)

        // spill BD^T into sBDT (alias over uR)
#pragma unroll
        for (int nf = 0; nf < 8; nf++) {
            int j = wid * 16 + g;
            int q = nf * 8 + 2 * tg;
            *(float2*)&sBDT[j * 68 + q]       = make_float2(bdf[nf].x, bdf[nf].y);
            *(float2*)&sBDT[(j + 8) * 68 + q] = make_float2(bdf[nf].z, bdf[nf].w);
        }
        __syncthreads();

        // softmax on in-register S^T
        float mk2[2];
#pragma unroll
        for (int half = 0; half < 2; half++) {
            int k = k0 + wm * 16 + g + half * 8;
            mk2[half] = (k >= MM)
                ? fminf(fmaxf(((float)(k - MM) + spanv * (float)QQ) * (1.0f / 33.0f), 0.0f), 1.0f)
                : 1.0f;
        }
        const bool lastT = (t == ntiles - 1);
#pragma unroll
        for (int nf = 0; nf < 4; nf++) {
            float sv[4] = {sf[nf].x, sf[nf].y, sf[nf].z, sf[nf].w};
            uint32_t pt[4];
#pragma unroll
            for (int e = 0; e < 4; e++) {
                int half = e >> 1, p = e & 1;
                int key = wm * 16 + g + half * 8;
                int q = wn * 32 + nf * 8 + 2 * tg + p;
                int j = key + 63 - q;
                float val = (sv[e] + sBDT[j * 68 + q] + sB1[j]) * (1.0f / 64.0f);
                float ex = __expf(val);
                if (lastT && (k0 + key > MM + q0 + q)) ex = 0.f;
                float em = ex * mk2[half];
                lfp[nf * 2 + p] += ex;
                lmp[nf * 2 + p] += em;
                pt[e] = f2tf(em);
            }
            int q = wn * 32 + nf * 8 + 2 * tg;
            int key = wm * 16 + g;
            *(uint2*)&uPT[key * 72 + q]       = make_uint2(pt[0], pt[1]);
            *(uint2*)&uPT[(key + 8) * 72 + q] = make_uint2(pt[2], pt[3]);
        }
        __syncthreads();

        // O^T += V^T * P^T
#pragma unroll
        for (int ks = 0; ks < 64; ks += 8) {
            uint32_t av[4];
            int m = wm * 16;
            av[0] = uV[(ks + tg) * 72 + m + g];
            av[1] = uV[(ks + tg) * 72 + m + g + 8];
            av[2] = uV[(ks + tg + 4) * 72 + m + g];
            av[3] = uV[(ks + tg + 4) * 72 + m + g + 8];
            uint32_t bp[4][2];
#pragma unroll
            for (int nf = 0; nf < 4; nf++) {
                int n = wn * 32 + nf * 8 + g;
                bp[nf][0] = uPT[(ks + tg) * 72 + n];
                bp[nf][1] = uPT[(ks + tg + 4) * 72 + n];
            }
#pragma unroll
            for (int nf = 0; nf < 4; nf++)
                mma_tf32(o[nf], av, bp[nf]);
        }
    }

    // reduce lf/lm over g lanes (lane bits 2..4)
#pragma unroll
    for (int s = 0; s < 8; s++) {
#pragma unroll
        for (int off = 4; off <= 16; off <<= 1) {
            lfp[s] += __shfl_xor_sync(0xffffffffu, lfp[s], off);
            lmp[s] += __shfl_xor_sync(0xffffffffu, lmp[s], off);
        }
    }
    if (g == 0) {
#pragma unroll
        for (int nf = 0; nf < 4; nf++) {
            int q = wn * 32 + nf * 8 + 2 * tg;
            *(float2*)&sRM[wm * 64 + q] = make_float2(lmp[nf * 2], lmp[nf * 2 + 1]);
            *(float2*)&sRF[wm * 64 + q] = make_float2(lfp[nf * 2], lfp[nf * 2 + 1]);
        }
    }
    __syncthreads();
    if (tid < 64) {
        float lm = sRM[tid] + sRM[64 + tid] + sRM[128 + tid] + sRM[192 + tid];
        float lf = sRF[tid] + sRF[64 + tid] + sRF[128 + tid] + sRF[192 + tid];
        sIv[tid] = 1.0f / (lm + 1e-8f * lf);
    }
    __syncthreads();

    // write output (transposed frags back to [q][d])
#pragma unroll
    for (int nf = 0; nf < 4; nf++) {
        int q = wn * 32 + nf * 8 + 2 * tg;
        int d = wm * 16 + g;
        float i0 = sIv[q], i1 = sIv[q + 1];
        size_t base0 = ((size_t)(b * QQ + q0 + q)) * HID + h * 64;
        size_t base1 = base0 + HID;
        Out[base0 + d]     = o[nf].x * i0;
        Out[base1 + d]     = o[nf].y * i1;
        Out[base0 + d + 8] = o[nf].z * i0;
        Out[base1 + d + 8] = o[nf].w * i1;
    }
}

// ---------------- launch -----------------------------------------------------
extern "C" void kernel_launch(void* const* d_in, const int* in_sizes, int n_in,
                              void* d_out, int out_size)
{
    const float* query     = (const float*)d_in[0];
    const float* memory    = (const float*)d_in[1];
    const float* Wq        = (const float*)d_in[2];
    const float* Wk        = (const float*)d_in[3];
    const float* Wv        = (const float*)d_in[4];
    const float* Wo        = (const float*)d_in[5];
    const float* Wr        = (const float*)d_in[6];
    const float* gamma_mem = (const float*)d_in[7];
    const float* beta_mem  = (const float*)d_in[8];
    const float* gamma_q   = (const float*)d_in[9];
    const float* beta_q    = (const float*)d_in[10];
    const float* rwb       = (const float*)d_in[11];
    const float* rrb       = (const float*)d_in[12];
    const float* span      = (const float*)d_in[13];
    float* out = (float*)d_out;

    float *kvln, *qln, *pe, *Qp, *Kp, *Vp, *Rel, *attn;
    cudaGetSymbolAddress((void**)&kvln, g_kvln);
    cudaGetSymbolAddress((void**)&qln,  g_qln);
    cudaGetSymbolAddress((void**)&pe,   g_pe);
    cudaGetSymbolAddress((void**)&Qp,   g_Qp);
    cudaGetSymbolAddress((void**)&Kp,   g_Kp);
    cudaGetSymbolAddress((void**)&Vp,   g_Vp);
    cudaGetSymbolAddress((void**)&Rel,  g_Rel);
    cudaGetSymbolAddress((void**)&attn, g_attn);

    cudaFuncSetAttribute(attn_tf32, cudaFuncAttributeMaxDynamicSharedMemorySize,
                         ATTN_SMEM_BYTES);

    ln_kv_kernel<<<BB * KK, 256>>>(memory, query, gamma_mem, beta_mem, kvln);
    ln_q_kernel <<<BB * QQ, 256>>>(query, gamma_q, beta_q, qln);
    posemb_kernel<<<KK, 256>>>(pe);

    sgemm_tf32<<<dim3(8, (BB * QQ) / 128), 256>>>(qln,  Wq, Qp);
    sgemm_tf32<<<dim3(8, (BB * KK) / 128), 256>>>(kvln, Wk, Kp);
    sgemm_tf32<<<dim3(8, (BB * KK) / 128), 256>>>(kvln, Wv, Vp);
    sgemm_tf32<<<dim3(8, KK / 128),        256>>>(pe,   Wr, Rel);

    attn_tf32<<<dim3(QQ / 64, BB * HH), 256, ATTN_SMEM_BYTES>>>(
        Qp, Kp, Vp, Rel, rwb, rrb, span, attn);

    sgemm_tf32<<<dim3(8, (BB * QQ) / 128), 256>>>(attn, Wo, out);
}

// round 8
// speedup vs baseline: 2.6712x; 1.0189x over previous
#include <cuda_runtime.h>
#include <cuda_bf16.h>
#include <math.h>
#include <stdint.h>

// Problem constants
constexpr int BB = 2;
constexpr int QQ = 2048;
constexpr int MM = 2048;
constexpr int HH = 16;
constexpr int HID = 1024;      // H*D
constexpr int KK = MM + QQ;    // 4096

// ---------------- tf32 mma helpers ------------------------------------------
__device__ __forceinline__ uint32_t f2tf(float f)
{
    uint32_t r;
    asm("cvt.rna.tf32.f32 %0, %1;" : "=r"(r) : "f"(f));
    return r;
}
__device__ __forceinline__ void mma_tf32(float4& c, const uint32_t* a, const uint32_t* b)
{
    asm volatile("mma.sync.aligned.m16n8k8.row.col.f32.tf32.tf32.f32 "
                 "{%0,%1,%2,%3}, {%4,%5,%6,%7}, {%8,%9}, {%0,%1,%2,%3};\n"
                 : "+f"(c.x), "+f"(c.y), "+f"(c.z), "+f"(c.w)
                 : "r"(a[0]), "r"(a[1]), "r"(a[2]), "r"(a[3]),
                   "r"(b[0]), "r"(b[1]));
}
__device__ __forceinline__ void cpa16(void* s, const void* g)
{
    uint32_t sa = (uint32_t)__cvta_generic_to_shared(s);
    asm volatile("cp.async.cg.shared.global [%0], [%1], 16;\n" :: "r"(sa), "l"(g));
}
__device__ __forceinline__ float ex2_approx(float x)
{
    float r;
    asm("ex2.approx.f32 %0, %1;" : "=f"(r) : "f"(x));
    return r;
}

// ---------------- scratch (device globals; no allocations allowed) ----------
__device__ float g_kvln[(size_t)BB * KK * HID];
__device__ float g_qln [(size_t)BB * QQ * HID];
__device__ float g_pe  [(size_t)KK * HID];
__device__ float g_Qp  [(size_t)BB * QQ * HID];
__device__ float g_Kp  [(size_t)BB * KK * HID];
__device__ float g_Vp  [(size_t)BB * KK * HID];
__device__ float g_Rel [(size_t)KK * HID];
__device__ float g_attn[(size_t)BB * QQ * HID];

// ---------------- LayerNorm over rows of length 1024 ------------------------
__device__ __forceinline__ void ln_row_1024(const float* __restrict__ src,
                                            float* __restrict__ dst,
                                            const float* __restrict__ gamma,
                                            const float* __restrict__ beta)
{
    __shared__ float red[16];
    int tid = threadIdx.x;                    // 256 threads, 4 floats each
    float4 v = ((const float4*)src)[tid];
    float s1 = v.x + v.y + v.z + v.w;
    float s2 = v.x*v.x + v.y*v.y + v.z*v.z + v.w*v.w;
#pragma unroll
    for (int off = 16; off; off >>= 1) {
        s1 += __shfl_xor_sync(0xffffffffu, s1, off);
        s2 += __shfl_xor_sync(0xffffffffu, s2, off);
    }
    if ((tid & 31) == 0) { red[tid >> 5] = s1; red[8 + (tid >> 5)] = s2; }
    __syncthreads();
    if (tid == 0) {
        float a = 0.f, b = 0.f;
#pragma unroll
        for (int i = 0; i < 8; i++) { a += red[i]; b += red[8 + i]; }
        float mu  = a * (1.0f / 1024.0f);
        float var = b * (1.0f / 1024.0f) - mu * mu;
        red[0] = mu;
        red[1] = rsqrtf(var + 1e-3f);
    }
    __syncthreads();
    float mu = red[0], sc = red[1];
    float4 g  = ((const float4*)gamma)[tid];
    float4 bb = ((const float4*)beta)[tid];
    float4 o;
    o.x = (v.x - mu) * sc * g.x + bb.x;
    o.y = (v.y - mu) * sc * g.y + bb.y;
    o.z = (v.z - mu) * sc * g.z + bb.z;
    o.w = (v.w - mu) * sc * g.w + bb.w;
    ((float4*)dst)[tid] = o;
}

__global__ __launch_bounds__(256)
void ln_kv_kernel(const float* __restrict__ mem, const float* __restrict__ qry,
                  const float* __restrict__ gamma, const float* __restrict__ beta,
                  float* __restrict__ out)
{
    int row = blockIdx.x;
    int b = row / KK, r = row % KK;
    const float* src = (r < MM) ? (mem + ((size_t)b * MM + r) * HID)
                                : (qry + ((size_t)b * QQ + (r - MM)) * HID);
    ln_row_1024(src, out + (size_t)row * HID, gamma, beta);
}

__global__ __launch_bounds__(256)
void ln_q_kernel(const float* __restrict__ qry,
                 const float* __restrict__ gamma, const float* __restrict__ beta,
                 float* __restrict__ out)
{
    int row = blockIdx.x;
    ln_row_1024(qry + (size_t)row * HID, out + (size_t)row * HID, gamma, beta);
}

// ---------------- sinusoidal relative position embedding (fast MUFU) --------
__global__ __launch_bounds__(512)
void posemb_kernel(float* __restrict__ pe)
{
    int j = blockIdx.x;                        // 0 .. KK-1
    int i = threadIdx.x;                       // 0 .. 511
    float pos = (float)(KK - 1 - j);
    // inv_freq = 10000^(-i/512) = 2^(-log2(1e4)/512 * i)
    const float c2 = -13.287712379549449f / 512.0f;
    float invf = ex2_approx(c2 * (float)i);
    float ang  = pos * invf;
    // Cody-Waite mod 2*pi, then HW sincos
    float k = rintf(ang * 0.15915494309189535f);
    float a = fmaf(k, -6.2831854820251465f, ang);     // hi(2pi)
    a = fmaf(k, 1.7484555e-7f, a);                    // -(lo) correction
    float s, cc;
    __sincosf(a, &s, &cc);
    pe[(size_t)j * HID + i]       = s;
    pe[(size_t)j * HID + 512 + i] = cc;
}

// ---------------- tf32 SGEMM: C[M,1024] = A[M,1024]*B[1024,1024] ------------
// 128x128 tile, BK=16, 8 warps (2m x 4n), warp tile 64x32, m16n8k8 mma.
// 3-stage cp.async pipeline, raw fp32 in smem, cvt.rna at fragment load.
constexpr int GA_STRIDE = 20;     // As row stride (floats)
constexpr int GB_STRIDE = 136;    // Bs row stride (floats)
constexpr int GA_BUF = 128 * GA_STRIDE;   // 2560
constexpr int GB_BUF = 16 * GB_STRIDE;    // 2176
constexpr int GEMM_SMEM_BYTES = 3 * (GA_BUF + GB_BUF) * 4;   // 56,832 B

__global__ __launch_bounds__(256, 2)
void sgemm_tf32(const float* __restrict__ A, const float* __restrict__ B,
                float* __restrict__ C)
{
    extern __shared__ float gsm[];
    float* sA = gsm;                  // 3 x [128][20]
    float* sB = gsm + 3 * GA_BUF;     // 3 x [16][136]
    const int tid = threadIdx.x;
    const int lane = tid & 31, wid = tid >> 5;
    const int g = lane >> 2, tg = lane & 3;
    const int wm = (wid & 1) * 64, wn = (wid >> 1) * 32;
    const int row0 = blockIdx.y * 128, col0 = blockIdx.x * 128;

    // copy mapping (per stage: A 512 float4, B 512 float4; 2+2 per thread)
    const int af4a = tid,        af4b = tid + 256;
    const int ar_a = af4a >> 2,  ac_a = (af4a & 3) << 2;
    const int ar_b = af4b >> 2,  ac_b = (af4b & 3) << 2;
    const int br_a = af4a >> 5,  bc_a = (af4a & 31) << 2;
    const int br_b = af4b >> 5,  bc_b = (af4b & 31) << 2;

    auto issue = [&](int buf, int k0) {
        float* a = sA + buf * GA_BUF;
        float* bfp = sB + buf * GB_BUF;
        cpa16(&a[ar_a * GA_STRIDE + ac_a], &A[(size_t)(row0 + ar_a) * 1024 + k0 + ac_a]);
        cpa16(&a[ar_b * GA_STRIDE + ac_b], &A[(size_t)(row0 + ar_b) * 1024 + k0 + ac_b]);
        cpa16(&bfp[br_a * GB_STRIDE + bc_a], &B[(size_t)(k0 + br_a) * 1024 + col0 + bc_a]);
        cpa16(&bfp[br_b * GB_STRIDE + bc_b], &B[(size_t)(k0 + br_b) * 1024 + col0 + bc_b]);
    };

    issue(0, 0);
    asm volatile("cp.async.commit_group;\n" ::: "memory");
    issue(1, 16);
    asm volatile("cp.async.commit_group;\n" ::: "memory");

    float4 acc[4][4];
#pragma unroll
    for (int i = 0; i < 4; i++)
#pragma unroll
        for (int j = 0; j < 4; j++) acc[i][j] = make_float4(0.f, 0.f, 0.f, 0.f);

    for (int it = 0; it < 64; it++) {
        asm volatile("cp.async.wait_group 1;\n" ::: "memory");
        __syncthreads();
        if (it + 2 < 64) issue((it + 2) % 3, (it + 2) * 16);
        asm volatile("cp.async.commit_group;\n" ::: "memory");

        const float* a = sA + (it % 3) * GA_BUF;
        const float* bs = sB + (it % 3) * GB_BUF;
#pragma unroll
        for (int kk = 0; kk < 16; kk += 8) {
            uint32_t af[4][4], bf[4][2];
#pragma unroll
            for (int mf = 0; mf < 4; mf++) {
                int m = wm + mf * 16;
                af[mf][0] = f2tf(a[(m + g) * GA_STRIDE + kk + tg]);
                af[mf][1] = f2tf(a[(m + g + 8) * GA_STRIDE + kk + tg]);
                af[mf][2] = f2tf(a[(m + g) * GA_STRIDE + kk + tg + 4]);
                af[mf][3] = f2tf(a[(m + g + 8) * GA_STRIDE + kk + tg + 4]);
            }
#pragma unroll
            for (int nf = 0; nf < 4; nf++) {
                int n = wn + nf * 8;
                bf[nf][0] = f2tf(bs[(kk + tg) * GB_STRIDE + n + g]);
                bf[nf][1] = f2tf(bs[(kk + tg + 4) * GB_STRIDE + n + g]);
            }
#pragma unroll
            for (int mf = 0; mf < 4; mf++)
#pragma unroll
                for (int nf = 0; nf < 4; nf++)
                    mma_tf32(acc[mf][nf], af[mf], bf[nf]);
        }
    }
#pragma unroll
    for (int mf = 0; mf < 4; mf++) {
#pragma unroll
        for (int nf = 0; nf < 4; nf++) {
            int r = row0 + wm + mf * 16 + g;
            int c = col0 + wn + nf * 8 + 2 * tg;
            *(float2*)&C[(size_t)r * 1024 + c] = make_float2(acc[mf][nf].x, acc[mf][nf].y);
            *(float2*)&C[(size_t)(r + 8) * 1024 + c] = make_float2(acc[mf][nf].z, acc[mf][nf].w);
        }
    }
}

// ---------------- fused relative attention (tf32 mma, transposed tiles) -----
// grid: (Q/64, B*H); 256 threads, 8 warps.
// S^T = K*Qw^T, BD^T = Rel*Qw^T (+rank-1 bd1), O^T = V^T*P^T.
constexpr int AT_SQ  = 0;       // Qw^T [64 d][72]  tf32
constexpr int AT_SK  = 4608;    // K    [64 k][68]  tf32
constexpr int AT_SV  = 8960;    // V    [64 k][72]  tf32
constexpr int AT_SR  = 13568;   // Rel  [128 j][68] tf32 / BD^T f32 (alias)
constexpr int AT_SPT = 22272;   // P^T  [64 k][72]  tf32
constexpr int AT_SB1 = 26880;   // bd1 halves [256] f32
constexpr int AT_SDL = 27136;   // dl   [64]  f32
constexpr int AT_SRM = 27200;   // lm red [4][64]
constexpr int AT_SRF = 27456;   // lf red [4][64]
constexpr int AT_SIV = 27712;   // inv  [64]
constexpr int AT_TOT = 27776;
constexpr int ATTN_SMEM_BYTES = AT_TOT * 4;     // 111,104 B -> 2 CTAs/SM

__global__ __launch_bounds__(256, 2)
void attn_tf32(const float* __restrict__ Qp, const float* __restrict__ Kp,
               const float* __restrict__ Vp, const float* __restrict__ Rel,
               const float* __restrict__ rwb, const float* __restrict__ rrb,
               const float* __restrict__ span, float* __restrict__ Out)
{
    extern __shared__ float sm[];
    uint32_t* uQ  = (uint32_t*)(sm + AT_SQ);
    uint32_t* uK  = (uint32_t*)(sm + AT_SK);
    uint32_t* uV  = (uint32_t*)(sm + AT_SV);
    uint32_t* uR  = (uint32_t*)(sm + AT_SR);
    float*   sBDT = sm + AT_SR;                  // alias over Rel
    uint32_t* uPT = (uint32_t*)(sm + AT_SPT);
    float* sB1 = sm + AT_SB1;
    float* sDl = sm + AT_SDL;
    float* sRM = sm + AT_SRM;
    float* sRF = sm + AT_SRF;
    float* sIv = sm + AT_SIV;

    const int tid = threadIdx.x;
    const int lane = tid & 31, wid = tid >> 5;
    const int g = lane >> 2, tg = lane & 3;
    const int wm = wid & 3;            // key/d strip (x16) for AD / PV
    const int wn = wid >> 2;           // q half (x32)
    const int q0 = blockIdx.x * 64;
    const int b = blockIdx.y >> 4, h = blockIdx.y & 15;
    const float spanv = span[h];

    if (tid < 64) sDl[tid] = rrb[h * 64 + tid] - rwb[h * 64 + tid];

    // stage Qw^T = (q + r_w_bias)^T, tf32 (once per CTA)
    for (int idx = tid; idx < 1024; idx += 256) {
        int qq = idx >> 4, d4 = (idx & 15) << 2;
        float4 qv = *(const float4*)&Qp[((size_t)(b * QQ + q0 + qq)) * HID + h * 64 + d4];
        float4 wb = *(const float4*)&rwb[h * 64 + d4];
        uQ[(d4 + 0) * 72 + qq] = f2tf(qv.x + wb.x);
        uQ[(d4 + 1) * 72 + qq] = f2tf(qv.y + wb.y);
        uQ[(d4 + 2) * 72 + qq] = f2tf(qv.z + wb.z);
        uQ[(d4 + 3) * 72 + qq] = f2tf(qv.w + wb.w);
    }

    float4 o[4];                       // out^T frags (d strip x q)
#pragma unroll
    for (int i = 0; i < 4; i++) o[i] = make_float4(0.f, 0.f, 0.f, 0.f);
    float lfp[8], lmp[8];
#pragma unroll
    for (int i = 0; i < 8; i++) { lfp[i] = 0.f; lmp[i] = 0.f; }

    const int ntiles = 33 + blockIdx.x;
    for (int t = 0; t < ntiles; t++) {
        const int k0 = t * 64;
        __syncthreads();               // prior-tile reads done (and Q stage at t=0)

        // stage K [key][68], V [key][72] (row-major, tf32)
        for (int idx = tid; idx < 1024; idx += 256) {
            int kk = idx >> 4, d4 = (idx & 15) << 2;
            size_t gofs = ((size_t)(b * KK + k0 + kk)) * HID + h * 64 + d4;
            float4 kv = *(const float4*)&Kp[gofs];
            *(uint4*)&uK[kk * 68 + d4] =
                make_uint4(f2tf(kv.x), f2tf(kv.y), f2tf(kv.z), f2tf(kv.w));
            float4 vv = *(const float4*)&Vp[gofs];
            *(uint4*)&uV[kk * 72 + d4] =
                make_uint4(f2tf(vv.x), f2tf(vv.y), f2tf(vv.z), f2tf(vv.w));
        }
        // stage Rel window [j][68], rows jbase..jbase+127, zero-pad past KK
        const int jbase = k0 + (QQ - 1) - (q0 + 63);
        for (int idx = tid; idx < 2048; idx += 256) {
            int jj = idx >> 4, d4 = (idx & 15) << 2;
            int j = jbase + jj;
            uint4 rt = make_uint4(0u, 0u, 0u, 0u);
            if (j < KK) {
                float4 rv = *(const float4*)&Rel[(size_t)j * HID + h * 64 + d4];
                rt = make_uint4(f2tf(rv.x), f2tf(rv.y), f2tf(rv.z), f2tf(rv.w));
            }
            *(uint4*)&uR[jj * 68 + d4] = rt;
        }
        __syncthreads();

        // bd1[j] = sum_d Rel[j][d] * dl[d]  (rank-1 r_r_bias term; all 256 thr)
        {
            int j = tid >> 1, half = tid & 1;
            const float* rr = (const float*)&uR[j * 68 + half * 32];
            const float* dd = &sDl[half * 32];
            float s = 0.f;
#pragma unroll
            for (int d4 = 0; d4 < 32; d4 += 4) {
                float4 r4 = *(const float4*)&rr[d4];
                float4 dl4 = *(const float4*)&dd[d4];
                s += r4.x * dl4.x + r4.y * dl4.y + r4.z * dl4.z + r4.w * dl4.w;
            }
            sB1[tid] = s;
        }

        // AD^T + BD^T mma (shared B-operand = Qw^T)
        float4 sf[4];                  // S^T frags (key strip x q)
        float4 bdf[8];                 // BD^T frags (j strip x 64 q)
#pragma unroll
        for (int i = 0; i < 4; i++) sf[i] = make_float4(0.f, 0.f, 0.f, 0.f);
#pragma unroll
        for (int i = 0; i < 8; i++) bdf[i] = make_float4(0.f, 0.f, 0.f, 0.f);
#pragma unroll
        for (int ks = 0; ks < 64; ks += 8) {
            uint32_t bq[8][2];
#pragma unroll
            for (int nf = 0; nf < 8; nf++) {
                int n = nf * 8 + g;
                bq[nf][0] = uQ[(ks + tg) * 72 + n];
                bq[nf][1] = uQ[(ks + tg + 4) * 72 + n];
            }
            uint32_t ak[4], ar[4];
            {
                int m = wm * 16;
                ak[0] = uK[(m + g) * 68 + ks + tg];
                ak[1] = uK[(m + g + 8) * 68 + ks + tg];
                ak[2] = uK[(m + g) * 68 + ks + tg + 4];
                ak[3] = uK[(m + g + 8) * 68 + ks + tg + 4];
            }
            {
                int m = wid * 16;
                ar[0] = uR[(m + g) * 68 + ks + tg];
                ar[1] = uR[(m + g + 8) * 68 + ks + tg];
                ar[2] = uR[(m + g) * 68 + ks + tg + 4];
                ar[3] = uR[(m + g + 8) * 68 + ks + tg + 4];
            }
#pragma unroll
            for (int nf = 0; nf < 4; nf++)
                mma_tf32(sf[nf], ak, bq[wn * 4 + nf]);
#pragma unroll
            for (int nf = 0; nf < 8; nf++)
                mma_tf32(bdf[nf], ar, bq[nf]);
        }
        __syncthreads();               // all uR reads done (mma + bd1)

        // spill BD^T into sBDT (alias over uR)
#pragma unroll
        for (int nf = 0; nf < 8; nf++) {
            int j = wid * 16 + g;
            int q = nf * 8 + 2 * tg;
            *(float2*)&sBDT[j * 68 + q]       = make_float2(bdf[nf].x, bdf[nf].y);
            *(float2*)&sBDT[(j + 8) * 68 + q] = make_float2(bdf[nf].z, bdf[nf].w);
        }
        __syncthreads();

        // softmax on in-register S^T
        float mk2[2];
#pragma unroll
        for (int half = 0; half < 2; half++) {
            int k = k0 + wm * 16 + g + half * 8;
            mk2[half] = (k >= MM)
                ? fminf(fmaxf(((float)(k - MM) + spanv * (float)QQ) * (1.0f / 33.0f), 0.0f), 1.0f)
                : 1.0f;
        }
        const bool lastT = (t == ntiles - 1);
#pragma unroll
        for (int nf = 0; nf < 4; nf++) {
            float sv[4] = {sf[nf].x, sf[nf].y, sf[nf].z, sf[nf].w};
            uint32_t pt[4];
#pragma unroll
            for (int e = 0; e < 4; e++) {
                int half = e >> 1, p = e & 1;
                int key = wm * 16 + g + half * 8;
                int q = wn * 32 + nf * 8 + 2 * tg + p;
                int j = key + 63 - q;
                float b1 = sB1[2 * j] + sB1[2 * j + 1];
                float val = (sv[e] + sBDT[j * 68 + q] + b1) * (1.0f / 64.0f);
                float ex = __expf(val);
                if (lastT && (k0 + key > MM + q0 + q)) ex = 0.f;
                float em = ex * mk2[half];
                lfp[nf * 2 + p] += ex;
                lmp[nf * 2 + p] += em;
                pt[e] = f2tf(em);
            }
            int q = wn * 32 + nf * 8 + 2 * tg;
            int key = wm * 16 + g;
            *(uint2*)&uPT[key * 72 + q]       = make_uint2(pt[0], pt[1]);
            *(uint2*)&uPT[(key + 8) * 72 + q] = make_uint2(pt[2], pt[3]);
        }
        __syncthreads();

        // O^T += V^T * P^T
#pragma unroll
        for (int ks = 0; ks < 64; ks += 8) {
            uint32_t av[4];
            int m = wm * 16;
            av[0] = uV[(ks + tg) * 72 + m + g];
            av[1] = uV[(ks + tg) * 72 + m + g + 8];
            av[2] = uV[(ks + tg + 4) * 72 + m + g];
            av[3] = uV[(ks + tg + 4) * 72 + m + g + 8];
            uint32_t bp[4][2];
#pragma unroll
            for (int nf = 0; nf < 4; nf++) {
                int n = wn * 32 + nf * 8 + g;
                bp[nf][0] = uPT[(ks + tg) * 72 + n];
                bp[nf][1] = uPT[(ks + tg + 4) * 72 + n];
            }
#pragma unroll
            for (int nf = 0; nf < 4; nf++)
                mma_tf32(o[nf], av, bp[nf]);
        }
    }

    // reduce lf/lm over g lanes (lane bits 2..4)
#pragma unroll
    for (int s = 0; s < 8; s++) {
#pragma unroll
        for (int off = 4; off <= 16; off <<= 1) {
            lfp[s] += __shfl_xor_sync(0xffffffffu, lfp[s], off);
            lmp[s] += __shfl_xor_sync(0xffffffffu, lmp[s], off);
        }
    }
    if (g == 0) {
#pragma unroll
        for (int nf = 0; nf < 4; nf++) {
            int q = wn * 32 + nf * 8 + 2 * tg;
            *(float2*)&sRM[wm * 64 + q] = make_float2(lmp[nf * 2], lmp[nf * 2 + 1]);
            *(float2*)&sRF[wm * 64 + q] = make_float2(lfp[nf * 2], lfp[nf * 2 + 1]);
        }
    }
    __syncthreads();
    if (tid < 64) {
        float lm = sRM[tid] + sRM[64 + tid] + sRM[128 + tid] + sRM[192 + tid];
        float lf = sRF[tid] + sRF[64 + tid] + sRF[128 + tid] + sRF[192 + tid];
        sIv[tid] = 1.0f / (lm + 1e-8f * lf);
    }
    __syncthreads();

    // write output (transposed frags back to [q][d])
#pragma unroll
    for (int nf = 0; nf < 4; nf++) {
        int q = wn * 32 + nf * 8 + 2 * tg;
        int d = wm * 16 + g;
        float i0 = sIv[q], i1 = sIv[q + 1];
        size_t base0 = ((size_t)(b * QQ + q0 + q)) * HID + h * 64;
        size_t base1 = base0 + HID;
        Out[base0 + d]     = o[nf].x * i0;
        Out[base1 + d]     = o[nf].y * i1;
        Out[base0 + d + 8] = o[nf].z * i0;
        Out[base1 + d + 8] = o[nf].w * i1;
    }
}

// ---------------- launch -----------------------------------------------------
extern "C" void kernel_launch(void* const* d_in, const int* in_sizes, int n_in,
                              void* d_out, int out_size)
{
    const float* query     = (const float*)d_in[0];
    const float* memory    = (const float*)d_in[1];
    const float* Wq        = (const float*)d_in[2];
    const float* Wk        = (const float*)d_in[3];
    const float* Wv        = (const float*)d_in[4];
    const float* Wo        = (const float*)d_in[5];
    const float* Wr        = (const float*)d_in[6];
    const float* gamma_mem = (const float*)d_in[7];
    const float* beta_mem  = (const float*)d_in[8];
    const float* gamma_q   = (const float*)d_in[9];
    const float* beta_q    = (const float*)d_in[10];
    const float* rwb       = (const float*)d_in[11];
    const float* rrb       = (const float*)d_in[12];
    const float* span      = (const float*)d_in[13];
    float* out = (float*)d_out;

    float *kvln, *qln, *pe, *Qp, *Kp, *Vp, *Rel, *attn;
    cudaGetSymbolAddress((void**)&kvln, g_kvln);
    cudaGetSymbolAddress((void**)&qln,  g_qln);
    cudaGetSymbolAddress((void**)&pe,   g_pe);
    cudaGetSymbolAddress((void**)&Qp,   g_Qp);
    cudaGetSymbolAddress((void**)&Kp,   g_Kp);
    cudaGetSymbolAddress((void**)&Vp,   g_Vp);
    cudaGetSymbolAddress((void**)&Rel,  g_Rel);
    cudaGetSymbolAddress((void**)&attn, g_attn);

    cudaFuncSetAttribute(attn_tf32, cudaFuncAttributeMaxDynamicSharedMemorySize,
                         ATTN_SMEM_BYTES);
    cudaFuncSetAttribute(sgemm_tf32, cudaFuncAttributeMaxDynamicSharedMemorySize,
                         GEMM_SMEM_BYTES);

    ln_kv_kernel<<<BB * KK, 256>>>(memory, query, gamma_mem, beta_mem, kvln);
    ln_q_kernel <<<BB * QQ, 256>>>(query, gamma_q, beta_q, qln);
    posemb_kernel<<<KK, 512>>>(pe);

    sgemm_tf32<<<dim3(8, (BB * QQ) / 128), 256, GEMM_SMEM_BYTES>>>(qln,  Wq, Qp);
    sgemm_tf32<<<dim3(8, (BB * KK) / 128), 256, GEMM_SMEM_BYTES>>>(kvln, Wk, Kp);
    sgemm_tf32<<<dim3(8, (BB * KK) / 128), 256, GEMM_SMEM_BYTES>>>(kvln, Wv, Vp);
    sgemm_tf32<<<dim3(8, KK / 128),        256, GEMM_SMEM_BYTES>>>(pe,   Wr, Rel);

    attn_tf32<<<dim3(QQ / 64, BB * HH), 256, ATTN_SMEM_BYTES>>>(
        Qp, Kp, Vp, Rel, rwb, rrb, span, attn);

    sgemm_tf32<<<dim3(8, (BB * QQ) / 128), 256, GEMM_SMEM_BYTES>>>(attn, Wo, out);
}